// round 1
// baseline (speedup 1.0000x reference)
#include <cuda_runtime.h>
#include <cstdint>
#include <cstddef>

#define D_MODEL 1024
#define N_HEADS 16
#define BATCH   4
#define SEQ     2048
#define DK      64
#define M_ROWS  (BATCH * SEQ)   // 8192

// Scratch (static device arrays — allocation-free per harness rules)
__device__ float g_Q[BATCH * N_HEADS * SEQ * DK];   // [B,H,T,dk]
__device__ float g_K[BATCH * N_HEADS * SEQ * DK];
__device__ float g_V[BATCH * N_HEADS * SEQ * DK];
__device__ float g_A[BATCH * SEQ * D_MODEL];        // attention out, [B,T,C]

// ----------------------------------------------------------------------------
// GEMM: out[M,N] = A[M,K] @ W[K,N] + bias[N]
// split=1: scatter output into [B,H,T,dk] layout (head split)
// Tile: 128x64, BK=16, 256 threads, 8x4 microtile per thread.
// ----------------------------------------------------------------------------
#define GBM 128
#define GBN 64
#define GBK 16

__global__ __launch_bounds__(256) void gemm_proj(
    const float* __restrict__ A, const float* __restrict__ W,
    const float* __restrict__ bias, float* __restrict__ out, int split)
{
    __shared__ float As[GBK][GBM];       // A tile, transposed: As[k][m]
    __shared__ float Bs[GBK][GBN + 4];   // W tile

    const int tid = threadIdx.x;
    const int tx  = tid & 15;            // 0..15 -> N microtiles
    const int ty  = tid >> 4;            // 0..15 -> M microtiles
    const int m0  = blockIdx.y * GBM;
    const int n0  = blockIdx.x * GBN;

    // load indices
    const int ar = tid >> 1;             // 0..127
    const int ac = (tid & 1) << 3;       // 0 or 8
    const int br = tid >> 4;             // 0..15
    const int bc = (tid & 15) << 2;      // 0..60

    float acc[8][4];
    #pragma unroll
    for (int i = 0; i < 8; i++)
        #pragma unroll
        for (int j = 0; j < 4; j++) acc[i][j] = 0.f;

    for (int k0 = 0; k0 < D_MODEL; k0 += GBK) {
        float4 a0 = *(const float4*)&A[(size_t)(m0 + ar) * D_MODEL + k0 + ac];
        float4 a1 = *(const float4*)&A[(size_t)(m0 + ar) * D_MODEL + k0 + ac + 4];
        *(float4*)&Bs[br][bc] = *(const float4*)&W[(size_t)(k0 + br) * D_MODEL + n0 + bc];
        As[ac + 0][ar] = a0.x; As[ac + 1][ar] = a0.y;
        As[ac + 2][ar] = a0.z; As[ac + 3][ar] = a0.w;
        As[ac + 4][ar] = a1.x; As[ac + 5][ar] = a1.y;
        As[ac + 6][ar] = a1.z; As[ac + 7][ar] = a1.w;
        __syncthreads();

        #pragma unroll
        for (int kk = 0; kk < GBK; kk++) {
            float a[8], b[4];
            *(float4*)&a[0] = *(float4*)&As[kk][ty * 8];
            *(float4*)&a[4] = *(float4*)&As[kk][ty * 8 + 4];
            *(float4*)&b[0] = *(float4*)&Bs[kk][tx * 4];
            #pragma unroll
            for (int i = 0; i < 8; i++)
                #pragma unroll
                for (int j = 0; j < 4; j++)
                    acc[i][j] = fmaf(a[i], b[j], acc[i][j]);
        }
        __syncthreads();
    }

    #pragma unroll
    for (int i = 0; i < 8; i++) {
        const int m = m0 + ty * 8 + i;
        #pragma unroll
        for (int j = 0; j < 4; j++) {
            const int n = n0 + tx * 4 + j;
            const float v = acc[i][j] + bias[n];
            if (split) {
                const int b = m >> 11;        // /SEQ
                const int t = m & (SEQ - 1);
                const int h = n >> 6;         // /DK
                const int d = n & (DK - 1);
                out[(((size_t)b * N_HEADS + h) * SEQ + t) * DK + d] = v;
            } else {
                out[(size_t)m * D_MODEL + n] = v;
            }
        }
    }
}

// ----------------------------------------------------------------------------
// Flash-style causal attention. One block per (bh, q-tile of 64).
// Q/K/V are [B*H, T, dk]. Output written in [B,T,C] layout for final GEMM.
// 256 threads, each computes a 4x4 patch of the 64x64 S/P tile and 4x4 of O.
// ----------------------------------------------------------------------------
#define AQ  64
#define AKV 64
#define SMS 65   // smem row stride (pad to kill bank conflicts)

__global__ __launch_bounds__(256) void attn_kernel(
    const float* __restrict__ Q, const float* __restrict__ K,
    const float* __restrict__ V, float* __restrict__ out)
{
    extern __shared__ float sm[];
    float* Qs = sm;
    float* Ks = Qs + AQ  * SMS;
    float* Vs = Ks + AKV * SMS;
    float* Ps = Vs + AKV * SMS;

    const int bh = blockIdx.y;
    const int qt = blockIdx.x;
    const int q0 = qt * AQ;
    const int tid = threadIdx.x;
    const int tx  = tid & 15;
    const int ty  = tid >> 4;

    const float* Qb = Q + (size_t)bh * SEQ * DK;
    const float* Kb = K + (size_t)bh * SEQ * DK;
    const float* Vb = V + (size_t)bh * SEQ * DK;

    // Load Q tile (64 x 64)
    for (int idx = tid; idx < AQ * (DK / 4); idx += 256) {
        const int r = idx >> 4;
        const int c = (idx & 15) << 2;
        float4 v = *(const float4*)&Qb[(size_t)(q0 + r) * DK + c];
        float* p = &Qs[r * SMS + c];
        p[0] = v.x; p[1] = v.y; p[2] = v.z; p[3] = v.w;
    }

    float m_i[4], l_i[4], acc[4][4];
    #pragma unroll
    for (int i = 0; i < 4; i++) {
        m_i[i] = -1e30f; l_i[i] = 0.f;
        #pragma unroll
        for (int j = 0; j < 4; j++) acc[i][j] = 0.f;
    }

    for (int kt = 0; kt <= qt; kt++) {
        const int k0 = kt * AKV;
        __syncthreads();  // previous iter's Ks/Vs/Ps readers done (also covers Qs on kt=0)

        for (int idx = tid; idx < AKV * (DK / 4); idx += 256) {
            const int r = idx >> 4;
            const int c = (idx & 15) << 2;
            float4 kv = *(const float4*)&Kb[(size_t)(k0 + r) * DK + c];
            float* pk = &Ks[r * SMS + c];
            pk[0] = kv.x; pk[1] = kv.y; pk[2] = kv.z; pk[3] = kv.w;
            float4 vv = *(const float4*)&Vb[(size_t)(k0 + r) * DK + c];
            float* pv = &Vs[r * SMS + c];
            pv[0] = vv.x; pv[1] = vv.y; pv[2] = vv.z; pv[3] = vv.w;
        }
        __syncthreads();

        // S = Q @ K^T
        float s[4][4];
        #pragma unroll
        for (int i = 0; i < 4; i++)
            #pragma unroll
            for (int j = 0; j < 4; j++) s[i][j] = 0.f;

        #pragma unroll 4
        for (int kk = 0; kk < DK; kk++) {
            float a[4], b[4];
            #pragma unroll
            for (int i = 0; i < 4; i++) a[i] = Qs[(ty * 4 + i) * SMS + kk];
            #pragma unroll
            for (int j = 0; j < 4; j++) b[j] = Ks[(tx * 4 + j) * SMS + kk];
            #pragma unroll
            for (int i = 0; i < 4; i++)
                #pragma unroll
                for (int j = 0; j < 4; j++)
                    s[i][j] = fmaf(a[i], b[j], s[i][j]);
        }

        // scale + causal mask (only the diagonal tile needs masking)
        const bool diag = (kt == qt);
        float rmax[4];
        #pragma unroll
        for (int i = 0; i < 4; i++) {
            const int qi = q0 + ty * 4 + i;
            #pragma unroll
            for (int j = 0; j < 4; j++) {
                float v = s[i][j] * 0.125f;   // 1/sqrt(64)
                if (diag && (k0 + tx * 4 + j) > qi) v = -1e30f;
                s[i][j] = v;
            }
            rmax[i] = fmaxf(fmaxf(s[i][0], s[i][1]), fmaxf(s[i][2], s[i][3]));
        }
        // row-max across the 16 threads (tx group is 16 contiguous lanes)
        #pragma unroll
        for (int off = 8; off >= 1; off >>= 1)
            #pragma unroll
            for (int i = 0; i < 4; i++)
                rmax[i] = fmaxf(rmax[i], __shfl_xor_sync(0xffffffffu, rmax[i], off));

        float rsum[4];
        #pragma unroll
        for (int i = 0; i < 4; i++) {
            const float mnew = fmaxf(m_i[i], rmax[i]);
            const float sc   = __expf(m_i[i] - mnew);
            float rs = 0.f;
            #pragma unroll
            for (int j = 0; j < 4; j++) {
                const float p = __expf(s[i][j] - mnew);
                s[i][j] = p;
                rs += p;
            }
            rsum[i] = rs;
            m_i[i] = mnew;
            l_i[i] *= sc;
            #pragma unroll
            for (int j = 0; j < 4; j++) acc[i][j] *= sc;
        }
        #pragma unroll
        for (int off = 8; off >= 1; off >>= 1)
            #pragma unroll
            for (int i = 0; i < 4; i++)
                rsum[i] += __shfl_xor_sync(0xffffffffu, rsum[i], off);
        #pragma unroll
        for (int i = 0; i < 4; i++) l_i[i] += rsum[i];

        // P -> shared
        #pragma unroll
        for (int i = 0; i < 4; i++)
            #pragma unroll
            for (int j = 0; j < 4; j++)
                Ps[(ty * 4 + i) * SMS + tx * 4 + j] = s[i][j];
        __syncthreads();

        // acc += P @ V
        #pragma unroll 4
        for (int c = 0; c < AKV; c++) {
            float p[4], v[4];
            #pragma unroll
            for (int i = 0; i < 4; i++) p[i] = Ps[(ty * 4 + i) * SMS + c];
            #pragma unroll
            for (int j = 0; j < 4; j++) v[j] = Vs[c * SMS + tx * 4 + j];
            #pragma unroll
            for (int i = 0; i < 4; i++)
                #pragma unroll
                for (int j = 0; j < 4; j++)
                    acc[i][j] = fmaf(p[i], v[j], acc[i][j]);
        }
    }

    // Write O / l into [B,T,C] layout
    const int b = bh >> 4;
    const int h = bh & (N_HEADS - 1);
    #pragma unroll
    for (int i = 0; i < 4; i++) {
        const int t = q0 + ty * 4 + i;
        const float inv = 1.0f / l_i[i];
        #pragma unroll
        for (int j = 0; j < 4; j++) {
            const int d = tx * 4 + j;
            out[((size_t)(b * SEQ + t)) * D_MODEL + h * DK + d] = acc[i][j] * inv;
        }
    }
}

// ----------------------------------------------------------------------------
extern "C" void kernel_launch(void* const* d_in, const int* in_sizes, int n_in,
                              void* d_out, int out_size)
{
    const float* x   = (const float*)d_in[0];
    // d_in[1] = mask (int32 causal tril) — causal structure is hardwired
    const float* w_q = (const float*)d_in[2];
    const float* b_q = (const float*)d_in[3];
    const float* w_k = (const float*)d_in[4];
    const float* b_k = (const float*)d_in[5];
    const float* w_v = (const float*)d_in[6];
    const float* b_v = (const float*)d_in[7];
    const float* w_o = (const float*)d_in[8];
    const float* b_o = (const float*)d_in[9];
    float* out = (float*)d_out;

    float *Qp, *Kp, *Vp, *Ap;
    cudaGetSymbolAddress((void**)&Qp, g_Q);
    cudaGetSymbolAddress((void**)&Kp, g_K);
    cudaGetSymbolAddress((void**)&Vp, g_V);
    cudaGetSymbolAddress((void**)&Ap, g_A);

    const int attn_smem = 4 * AQ * SMS * (int)sizeof(float);  // 66560 bytes
    cudaFuncSetAttribute(attn_kernel, cudaFuncAttributeMaxDynamicSharedMemorySize, attn_smem);

    dim3 gb(D_MODEL / GBN, M_ROWS / GBM);   // (16, 64)
    gemm_proj<<<gb, 256>>>(x, w_q, b_q, Qp, 1);
    gemm_proj<<<gb, 256>>>(x, w_k, b_k, Kp, 1);
    gemm_proj<<<gb, 256>>>(x, w_v, b_v, Vp, 1);

    attn_kernel<<<dim3(SEQ / AQ, BATCH * N_HEADS), 256, attn_smem>>>(Qp, Kp, Vp, Ap);

    gemm_proj<<<gb, 256>>>(Ap, w_o, b_o, out, 0);
}